// round 9
// baseline (speedup 1.0000x reference)
#include <cuda_runtime.h>
#include <cstdint>

// DCNv2 (R9): tensor-core einsum, restructured to fit 48KB dynamic smem so no
// cudaFuncSetAttribute is needed (suspected trigger of the R7/R8 container
// failures under the harness device-limit guards).
// out[16, px] = W[16x27] @ S[27, px] per (b,g); S from constant-shift bilinear
// sampling. Einsum via mma.sync.m16n8k8.tf32 with split-tf32
// (Wh*Sh + Wh*Sl + Wl*Sh) for fp32-class accuracy.
// CTA = 16x8 px tile, 128 threads, 43.5KB dyn smem -> 5 CTAs/SM.

namespace {
constexpr int Hdim = 160;
constexpr int Wdim = 160;
constexpr int TX = 16;                  // tile cols
constexpr int TY = 8;                   // tile rows
constexpr int HALO = 5;                 // shifts provably in [-4,4], +1 corner
constexpr int SMW = TX + 2 * HALO;      // 26
constexpr int SMH = TY + 2 * HALO;      // 18
constexpr int THREADS = 128;
constexpr int PXT = TX * TY;            // 128 px per tile
constexpr int SPITCH = 132;             // S row pitch in float2
// dynamic smem layout (bytes)
constexpr int S2_BYTES   = 32 * SPITCH * 8;          // 33792
constexpr int WH_OFF     = S2_BYTES;
constexpr int WL_OFF     = WH_OFF + 16 * 32 * 4;
constexpr int SMIN_OFF   = WL_OFF + 16 * 32 * 4;
constexpr int SMEM_BYTES = SMIN_OFF + 3 * SMH * SMW * 4;   // 43504 < 48KB
}

__device__ __forceinline__ float tf32_rna(float x) {
    uint32_t u;
    asm("cvt.rna.tf32.f32 %0, %1;" : "=r"(u) : "f"(x));
    return __uint_as_float(u);
}

__device__ __forceinline__ void mma_tf32(float& c0, float& c1, float& c2, float& c3,
                                         uint32_t a0, uint32_t a1, uint32_t a2, uint32_t a3,
                                         uint32_t b0, uint32_t b1) {
    asm("mma.sync.aligned.m16n8k8.row.col.f32.tf32.tf32.f32 "
        "{%0,%1,%2,%3}, {%4,%5,%6,%7}, {%8,%9}, {%0,%1,%2,%3};"
        : "+f"(c0), "+f"(c1), "+f"(c2), "+f"(c3)
        : "r"(a0), "r"(a1), "r"(a2), "r"(a3), "r"(b0), "r"(b1));
}

__global__ __launch_bounds__(THREADS)
void dcn_kernel(const float* __restrict__ input,
                const float* __restrict__ weight,
                const float* __restrict__ offset,
                float* __restrict__ out)
{
    extern __shared__ char dsm[];
    float2* S2   = reinterpret_cast<float2*>(dsm);           // [32][SPITCH] (hi,lo)
    float*  Wh   = reinterpret_cast<float*>(dsm + WH_OFF);   // [16][32]
    float*  Wl   = reinterpret_cast<float*>(dsm + WL_OFF);   // [16][32]
    float*  smin = reinterpret_cast<float*>(dsm + SMIN_OFF); // [3][SMH][SMW]

    const int bg = blockIdx.z;          // 0..47
    const int b  = bg / 3;
    const int g  = bg % 3;
    const int tile_x = blockIdx.x * TX;
    const int tile_y = blockIdx.y * TY;
    const int tid = threadIdx.x;

    // ---- phase 0: weights (hi/lo split, zero-padded K=32) ----
    for (int i = tid; i < 16 * 32; i += THREADS) {
        const int o  = i >> 5;
        const int kk = i & 31;
        float w = 0.0f;
        if (kk < 27) {
            const int c = kk / 9, k = kk % 9;
            w = weight[k * 144 + (g * 16 + o) * 3 + c];
        }
        const float hi = tf32_rna(w);
        Wh[i] = hi;
        Wl[i] = w - hi;
    }
    // zero S rows 27..31 (read by MMA, never written by sampling)
    for (int i = tid; i < 5 * PXT; i += THREADS) {
        const int r = i / PXT, n = i % PXT;
        S2[(27 + r) * SPITCH + n] = make_float2(0.0f, 0.0f);
    }
    // stage input tile (+halo, zero pad outside image)
    const float* inb = input + (size_t)(b >> 1) * 9 * Hdim * Wdim
                             + (size_t)(g * 3) * Hdim * Wdim;
    for (int i = tid; i < 3 * SMH * SMW; i += THREADS) {
        const int c = i / (SMH * SMW);
        const int r = (i / SMW) % SMH;
        const int q = i % SMW;
        const int gy = tile_y + r - HALO;
        const int gx = tile_x + q - HALO;
        float v = 0.0f;
        if (gy >= 0 && gy < Hdim && gx >= 0 && gx < Wdim)
            v = inb[(size_t)c * Hdim * Wdim + gy * Wdim + gx];
        smin[i] = v;
    }

    // ---- shift constants (uniform across block) ----
    const float offy = __ldg(&offset[(b * 3 + g) * 2 + 0]);
    const float offx = __ldg(&offset[(b * 3 + g) * 2 + 1]);
    const float dyv = 1.0f + 3.0f / offy;   // |shift| for p = +-1; p=0 -> 0
    const float dxv = 1.0f + 3.0f / offx;
    const float fyMf = floorf(-dyv), fyPf = floorf(dyv);
    const float fxMf = floorf(-dxv), fxPf = floorf(dxv);
    const int fyM = (int)fyMf, fyP = (int)fyPf;
    const int fxM = (int)fxMf, fxP = (int)fxPf;
    const float wyM = -dyv - fyMf, wyP = dyv - fyPf;
    const float wxM = -dxv - fxMf, wxP = dxv - fxPf;

    __syncthreads();

    // ---- phase 1: sampling, 1 px/thread ----
    {
        const int x = tid & 15;
        const int y = tid >> 4;           // 0..7
        float samp[27];
        #pragma unroll
        for (int c = 0; c < 3; c++) {
            const float* Bc = smin + c * (SMH * SMW) + (y + HALO) * SMW + (x + HALO);
            const float* r0 = Bc + fyM * SMW;   // p_y=-1 rows
            const float* r1 = r0 + SMW;
            const float* q0 = Bc + fyP * SMW;   // p_y=+1 rows
            const float* q1 = q0 + SMW;

            #define HL(P, FX, WX) (fmaf((WX), (P)[(FX) + 1] - (P)[(FX)], (P)[(FX)]))
            #define VL(A, B2, W)  (fmaf((W), (B2) - (A), (A)))

            samp[c * 9 + 4] = Bc[0];
            samp[c * 9 + 3] = HL(Bc, fxM, wxM);
            samp[c * 9 + 5] = HL(Bc, fxP, wxP);
            samp[c * 9 + 1] = VL(r0[0], r1[0], wyM);
            samp[c * 9 + 0] = VL(HL(r0, fxM, wxM), HL(r1, fxM, wxM), wyM);
            samp[c * 9 + 2] = VL(HL(r0, fxP, wxP), HL(r1, fxP, wxP), wyM);
            samp[c * 9 + 7] = VL(q0[0], q1[0], wyP);
            samp[c * 9 + 6] = VL(HL(q0, fxM, wxM), HL(q1, fxM, wxM), wyP);
            samp[c * 9 + 8] = VL(HL(q0, fxP, wxP), HL(q1, fxP, wxP), wyP);
            #undef HL
            #undef VL
        }
        #pragma unroll
        for (int kk = 0; kk < 27; kk++) {
            const float s  = samp[kk];
            const float hi = tf32_rna(s);
            S2[kk * SPITCH + tid] = make_float2(hi, s - hi);
        }
    }

    __syncthreads();

    // ---- phase 2: MMA. 4 warps x 4 n-blocks of 8 px; K = 32 (4 k-blocks) ----
    {
        const int lane = tid & 31;
        const int warp = tid >> 5;        // 0..3
        const int tig  = lane & 3;        // thread-in-group
        const int gid  = lane >> 2;       // group id (0..7)

        // A fragments (weights), loaded once
        uint32_t ah[4][4], al[4][4];
        #pragma unroll
        for (int kb = 0; kb < 4; kb++) {
            const int kc0 = kb * 8 + tig;
            const int kc1 = kc0 + 4;
            ah[kb][0] = __float_as_uint(Wh[gid * 32 + kc0]);
            ah[kb][1] = __float_as_uint(Wh[(gid + 8) * 32 + kc0]);
            ah[kb][2] = __float_as_uint(Wh[gid * 32 + kc1]);
            ah[kb][3] = __float_as_uint(Wh[(gid + 8) * 32 + kc1]);
            al[kb][0] = __float_as_uint(Wl[gid * 32 + kc0]);
            al[kb][1] = __float_as_uint(Wl[(gid + 8) * 32 + kc0]);
            al[kb][2] = __float_as_uint(Wl[gid * 32 + kc1]);
            al[kb][3] = __float_as_uint(Wl[(gid + 8) * 32 + kc1]);
        }

        #pragma unroll
        for (int j = 0; j < 4; j++) {
            const int nb = warp * 4 + j;  // 0..15
            const int n0 = nb * 8;        // covers 128 px
            float c0 = 0.0f, c1 = 0.0f, c2 = 0.0f, c3 = 0.0f;
            #pragma unroll
            for (int kb = 0; kb < 4; kb++) {
                const float2 p0 = S2[(kb * 8 + tig) * SPITCH + n0 + gid];
                const float2 p1 = S2[(kb * 8 + tig + 4) * SPITCH + n0 + gid];
                const uint32_t b0h = __float_as_uint(p0.x);
                const uint32_t b1h = __float_as_uint(p1.x);
                const uint32_t b0l = __float_as_uint(p0.y);
                const uint32_t b1l = __float_as_uint(p1.y);
                mma_tf32(c0, c1, c2, c3, ah[kb][0], ah[kb][1], ah[kb][2], ah[kb][3], b0h, b1h);
                mma_tf32(c0, c1, c2, c3, ah[kb][0], ah[kb][1], ah[kb][2], ah[kb][3], b0l, b1l);
                mma_tf32(c0, c1, c2, c3, al[kb][0], al[kb][1], al[kb][2], al[kb][3], b0h, b1h);
            }
            // store: px pair (n0+2*tig, +1) -> same output row
            const int px0 = n0 + 2 * tig;
            const int gy = tile_y + (px0 >> 4);
            const int gx = tile_x + (px0 & 15);
            float* base = out + (size_t)(b * 48 + g * 16 + gid) * (Hdim * Wdim)
                              + gy * Wdim + gx;
            *reinterpret_cast<float2*>(base) = make_float2(c0, c1);
            *reinterpret_cast<float2*>(base + (size_t)8 * Hdim * Wdim) = make_float2(c2, c3);
        }
    }
}

extern "C" void kernel_launch(void* const* d_in, const int* in_sizes, int n_in,
                              void* d_out, int out_size)
{
    const float* input  = (const float*)d_in[0];
    const float* weight = (const float*)d_in[1];
    const float* offset = (const float*)d_in[2];
    float* out = (float*)d_out;

    dim3 grid(Wdim / TX, Hdim / TY, 48);   // 10 x 20 x 48
    dcn_kernel<<<grid, THREADS, SMEM_BYTES>>>(input, weight, offset, out);
}